// round 1
// baseline (speedup 1.0000x reference)
#include <cuda_runtime.h>
#include <cuda_bf16.h>
#include <math.h>

// Problem constants
#define N 4096
#define D 256
#define H 4

// ---------------- device scratch (no cudaMalloc allowed) ----------------
__device__ float g_h[N * D];        // h = x*conv_w + conv_b          (4 MB)
__device__ float g_s1[N * H];       // per-row query scores  [N][4]
__device__ float g_s2[N * H];       // per-row key scores    [N][4]
__device__ float g_G[H];            // global max of s2 per head
__device__ float g_W[(size_t)N * N];// combined head-folded weights   (64 MB)
__device__ float g_O[N * D];        // aggregation result (= mean over heads)

// ---------------- helpers ----------------
__device__ __forceinline__ float elu_f(float x) {
    return x > 0.f ? x : (__expf(x) - 1.f);
}

// ---------------- kernel 1: h, s1, s2 ----------------
__global__ void k_prep(const float* __restrict__ x,
                       const float* __restrict__ cw,
                       const float* __restrict__ cb,
                       const float* __restrict__ a) {
    int i = blockIdx.x;
    int d = threadIdx.x;                     // 256 threads = D
    float hv = x[(size_t)i * D + d] * cw[0] + cb[0];
    g_h[(size_t)i * D + d] = hv;

    __shared__ float red[D];
    for (int hh = 0; hh < H; hh++) {
        // s1 = dot(h_row, a1[hh])
        red[d] = hv * a[hh * (2 * D) + d];
        __syncthreads();
        for (int s = D / 2; s > 0; s >>= 1) {
            if (d < s) red[d] += red[d + s];
            __syncthreads();
        }
        if (d == 0) g_s1[i * H + hh] = red[0];
        __syncthreads();
        // s2 = dot(h_row, a2[hh])
        red[d] = hv * a[hh * (2 * D) + D + d];
        __syncthreads();
        for (int s = D / 2; s > 0; s >>= 1) {
            if (d < s) red[d] += red[d + s];
            __syncthreads();
        }
        if (d == 0) g_s2[i * H + hh] = red[0];
        __syncthreads();
    }
}

// ---------------- kernel 2: global max of s2 per head ----------------
__global__ void k_gmax() {
    int tid = threadIdx.x;                   // 256 threads
    float4 m = make_float4(-3.0e38f, -3.0e38f, -3.0e38f, -3.0e38f);
    const float4* s24 = (const float4*)g_s2;
    for (int j = tid; j < N; j += 256) {
        float4 s = s24[j];
        m.x = fmaxf(m.x, s.x); m.y = fmaxf(m.y, s.y);
        m.z = fmaxf(m.z, s.z); m.w = fmaxf(m.w, s.w);
    }
    __shared__ float4 red[256];
    red[tid] = m;
    __syncthreads();
    for (int s = 128; s > 0; s >>= 1) {
        if (tid < s) {
            float4 a_ = red[tid], b = red[tid + s];
            red[tid] = make_float4(fmaxf(a_.x, b.x), fmaxf(a_.y, b.y),
                                   fmaxf(a_.z, b.z), fmaxf(a_.w, b.w));
        }
        __syncthreads();
    }
    if (tid == 0) {
        g_G[0] = red[0].x; g_G[1] = red[0].y;
        g_G[2] = red[0].z; g_G[3] = red[0].w;
    }
}

// ---------------- kernel 3: per-row masked softmax weights, head-folded ---
// One block per row i. Phase A: compute w[j][4] (masked, unnormalized,
// guaranteed <= 1 via the elu(s1+maxG) bound) into shared, sum Z per head.
// Phase B: W'[i,j] = sum_h w_h * (0.25/Z_h)   (0.25 = mean over heads)
__global__ void k_row(const int* __restrict__ adj) {
    extern __shared__ float sm[];
    float4* wc = (float4*)sm;                        // [N] float4 = 64 KB
    float4* zred = (float4*)(sm + N * 4);            // [256] float4 = 4 KB

    int i = blockIdx.x;
    int tid = threadIdx.x;                           // 256 threads

    __shared__ float s1v[H], Mv[H], iZ[H];
    if (tid < H) {
        float s1 = g_s1[i * H + tid];
        float xg = s1 + g_G[tid];
        s1v[tid] = s1;
        Mv[tid] = elu_f(xg);                         // >= masked max of e
    }
    __syncthreads();

    float s10 = s1v[0], s11 = s1v[1], s12 = s1v[2], s13 = s1v[3];
    float M0 = Mv[0], M1 = Mv[1], M2 = Mv[2], M3 = Mv[3];

    float Z0 = 0.f, Z1 = 0.f, Z2 = 0.f, Z3 = 0.f;
    const float4* s24 = (const float4*)g_s2;
    const int* arow = adj + (size_t)i * N;

    #pragma unroll 4
    for (int jt = 0; jt < N / 256; jt++) {
        int j = jt * 256 + tid;
        int mask = arow[j];
        float4 s2 = s24[j];
        float w0 = __expf(elu_f(s10 + s2.x) - M0);
        float w1 = __expf(elu_f(s11 + s2.y) - M1);
        float w2 = __expf(elu_f(s12 + s2.z) - M2);
        float w3 = __expf(elu_f(s13 + s2.w) - M3);
        if (mask <= 0) { w0 = 0.f; w1 = 0.f; w2 = 0.f; w3 = 0.f; }
        Z0 += w0; Z1 += w1; Z2 += w2; Z3 += w3;
        wc[j] = make_float4(w0, w1, w2, w3);
    }

    zred[tid] = make_float4(Z0, Z1, Z2, Z3);
    __syncthreads();
    for (int s = 128; s > 0; s >>= 1) {
        if (tid < s) {
            float4 a_ = zred[tid], b = zred[tid + s];
            zred[tid] = make_float4(a_.x + b.x, a_.y + b.y, a_.z + b.z, a_.w + b.w);
        }
        __syncthreads();
    }
    if (tid == 0) {
        float4 z = zred[0];
        iZ[0] = 0.25f / fmaxf(z.x, 1e-30f);
        iZ[1] = 0.25f / fmaxf(z.y, 1e-30f);
        iZ[2] = 0.25f / fmaxf(z.z, 1e-30f);
        iZ[3] = 0.25f / fmaxf(z.w, 1e-30f);
    }
    __syncthreads();

    float i0 = iZ[0], i1 = iZ[1], i2 = iZ[2], i3 = iZ[3];
    float* Wrow = g_W + (size_t)i * N;
    #pragma unroll 4
    for (int jt = 0; jt < N / 256; jt++) {
        int j = jt * 256 + tid;
        float4 w = wc[j];
        Wrow[j] = w.x * i0 + w.y * i1 + w.z * i2 + w.w * i3;
    }
}

// ---------------- kernel 4: O = W' @ h   (4096x4096 @ 4096x256, fp32) ----
#define BM 64
#define BN 64
#define BK 32
__global__ void __launch_bounds__(256) k_gemm() {
    __shared__ float As[BK][BM + 1];     // k-major W tile (padded)
    __shared__ float Bs[BK][BN];         // h tile

    int bx = blockIdx.x;                 // col tile 0..3
    int by = blockIdx.y;                 // row tile 0..63
    int tid = threadIdx.x;
    int tx = tid & 15;                   // 0..15 -> cols
    int ty = tid >> 4;                   // 0..15 -> rows

    float acc[4][4];
    #pragma unroll
    for (int i = 0; i < 4; i++)
        #pragma unroll
        for (int j = 0; j < 4; j++) acc[i][j] = 0.f;

    const float* Wp = g_W;
    const float* Hp = g_h;

    int ar = tid >> 3;                   // 0..31 row within tile
    int ak = (tid & 7) * 4;              // 0,4,...,28
    int bk = tid >> 4;                   // 0..15
    int bc = (tid & 15) * 4;             // 0,4,...,60

    for (int k0 = 0; k0 < N; k0 += BK) {
        // load W tile: 64 rows x 32 k, store k-major
        #pragma unroll
        for (int l = 0; l < 2; l++) {
            int row = ar + l * 32;
            float4 v = *(const float4*)&Wp[(size_t)(by * BM + row) * N + k0 + ak];
            As[ak + 0][row] = v.x;
            As[ak + 1][row] = v.y;
            As[ak + 2][row] = v.z;
            As[ak + 3][row] = v.w;
        }
        // load h tile: 32 k x 64 cols
        #pragma unroll
        for (int l = 0; l < 2; l++) {
            int kk = bk + l * 16;
            float4 v = *(const float4*)&Hp[(size_t)(k0 + kk) * D + bx * BN + bc];
            *(float4*)&Bs[kk][bc] = v;
        }
        __syncthreads();

        #pragma unroll
        for (int kk = 0; kk < BK; kk++) {
            float af[4];
            #pragma unroll
            for (int i = 0; i < 4; i++) af[i] = As[kk][ty * 4 + i];
            float4 bv = *(float4*)&Bs[kk][tx * 4];
            float bf[4] = {bv.x, bv.y, bv.z, bv.w};
            #pragma unroll
            for (int i = 0; i < 4; i++)
                #pragma unroll
                for (int j = 0; j < 4; j++)
                    acc[i][j] = fmaf(af[i], bf[j], acc[i][j]);
        }
        __syncthreads();
    }

    #pragma unroll
    for (int i = 0; i < 4; i++) {
        int row = by * BM + ty * 4 + i;
        float4 v = make_float4(acc[i][0], acc[i][1], acc[i][2], acc[i][3]);
        *(float4*)&g_O[(size_t)row * D + bx * BN + tx * 4] = v;
    }
}

// ---------------- kernel 5: elu(0.5*(O+h)), row-normalize, +bias ----------
__global__ void k_final(const float* __restrict__ bias, float* __restrict__ out) {
    int i = blockIdx.x;
    int d = threadIdx.x;
    float v = 0.5f * (g_O[(size_t)i * D + d] + g_h[(size_t)i * D + d]);
    float u = v > 0.f ? v : expm1f(v);

    __shared__ float red[D];
    red[d] = u * u;
    __syncthreads();
    for (int s = D / 2; s > 0; s >>= 1) {
        if (d < s) red[d] += red[d + s];
        __syncthreads();
    }
    __shared__ float nrm;
    if (d == 0) nrm = fmaxf(sqrtf(red[0]), 1e-12f);
    __syncthreads();
    out[(size_t)i * D + d] = u / nrm + bias[d];
}

// ---------------- launcher ----------------
extern "C" void kernel_launch(void* const* d_in, const int* in_sizes, int n_in,
                              void* d_out, int out_size) {
    const float* x   = (const float*)d_in[0];
    const int*   adj = (const int*)d_in[1];
    const float* cw  = (const float*)d_in[2];
    const float* cb  = (const float*)d_in[3];
    const float* a   = (const float*)d_in[4];
    const float* bias= (const float*)d_in[5];
    float* out = (float*)d_out;

    k_prep<<<N, D>>>(x, cw, cb, a);
    k_gmax<<<1, 256>>>();

    int smem = N * 4 * sizeof(float) + 256 * 4 * sizeof(float);  // 69632
    cudaFuncSetAttribute(k_row, cudaFuncAttributeMaxDynamicSharedMemorySize, smem);
    k_row<<<N, 256, smem>>>(adj);

    dim3 grid(D / BN, N / BM);
    k_gemm<<<grid, 256>>>();

    k_final<<<N, D>>>(bias, out);
}

// round 3
// speedup vs baseline: 2.8981x; 2.8981x over previous
#include <cuda_runtime.h>
#include <cuda_bf16.h>
#include <math.h>
#include <cstdint>

// Problem constants
#define N 4096
#define D 256
#define H 4

// ---------------- device scratch (no cudaMalloc allowed) ----------------
__device__ float g_h[N * D];                    // h fp32 (4 MB)
__device__ __nv_bfloat16 g_hb[N * D];           // h bf16 row-major (2 MB)   B operand
__device__ float g_s1[N * H];
__device__ float g_s2[N * H];
__device__ float g_G[H];
__device__ __nv_bfloat16 g_Wb[(size_t)N * N];   // head-folded weights bf16 (32 MB)  A operand
__device__ float g_O[N * D];                    // aggregation result fp32 (4 MB)

// ---------------- helpers ----------------
__device__ __forceinline__ float elu_f(float x) {
    return x > 0.f ? x : (__expf(x) - 1.f);
}

__device__ __forceinline__ uint32_t smem_u32(const void* p) {
    uint32_t a;
    asm("{ .reg .u64 t; cvta.to.shared.u64 t, %1; cvt.u32.u64 %0, t; }" : "=r"(a) : "l"(p));
    return a;
}

__device__ __forceinline__ uint32_t sw128(uint32_t off) {
    return off ^ ((off >> 3) & 0x70);
}

__device__ __forceinline__ void cp_async16(uint32_t dst, const void* src) {
    asm volatile("cp.async.cg.shared.global [%0], [%1], 16;" :: "r"(dst), "l"(src) : "memory");
}
#define CP_COMMIT() asm volatile("cp.async.commit_group;" ::: "memory")
#define CP_WAIT(n)  asm volatile("cp.async.wait_group %0;" :: "n"(n) : "memory")

__device__ __forceinline__ void ldsm_x4(uint32_t addr, uint32_t& r0, uint32_t& r1,
                                        uint32_t& r2, uint32_t& r3) {
    asm volatile("ldmatrix.sync.aligned.m8n8.x4.shared.b16 {%0,%1,%2,%3}, [%4];"
                 : "=r"(r0), "=r"(r1), "=r"(r2), "=r"(r3) : "r"(addr));
}
__device__ __forceinline__ void ldsm_x4_t(uint32_t addr, uint32_t& r0, uint32_t& r1,
                                          uint32_t& r2, uint32_t& r3) {
    asm volatile("ldmatrix.sync.aligned.m8n8.x4.trans.shared.b16 {%0,%1,%2,%3}, [%4];"
                 : "=r"(r0), "=r"(r1), "=r"(r2), "=r"(r3) : "r"(addr));
}
__device__ __forceinline__ void mma_bf16(float& c0, float& c1, float& c2, float& c3,
                                         uint32_t a0, uint32_t a1, uint32_t a2, uint32_t a3,
                                         uint32_t b0, uint32_t b1) {
    asm volatile("mma.sync.aligned.m16n8k16.row.col.f32.bf16.bf16.f32 "
                 "{%0,%1,%2,%3}, {%4,%5,%6,%7}, {%8,%9}, {%0,%1,%2,%3};"
                 : "+f"(c0), "+f"(c1), "+f"(c2), "+f"(c3)
                 : "r"(a0), "r"(a1), "r"(a2), "r"(a3), "r"(b0), "r"(b1));
}

// ---------------- kernel 1: h, hb(bf16), s1, s2 ----------------
__global__ void k_prep(const float* __restrict__ x,
                       const float* __restrict__ cw,
                       const float* __restrict__ cb,
                       const float* __restrict__ a) {
    int i = blockIdx.x;
    int d = threadIdx.x;                     // 256 threads = D
    int lane = d & 31, warp = d >> 5;
    float hv = x[(size_t)i * D + d] * cw[0] + cb[0];
    g_h[(size_t)i * D + d] = hv;
    g_hb[(size_t)i * D + d] = __float2bfloat16_rn(hv);

    float p[8];
    #pragma unroll
    for (int hh = 0; hh < H; hh++) {
        p[hh]     = hv * a[hh * (2 * D) + d];
        p[hh + 4] = hv * a[hh * (2 * D) + D + d];
    }
    #pragma unroll
    for (int s = 16; s > 0; s >>= 1)
        #pragma unroll
        for (int k = 0; k < 8; k++)
            p[k] += __shfl_down_sync(0xFFFFFFFFu, p[k], s);

    __shared__ float ws[8][8];
    if (lane == 0)
        #pragma unroll
        for (int k = 0; k < 8; k++) ws[warp][k] = p[k];
    __syncthreads();
    if (d < 8) {
        float s = 0.f;
        #pragma unroll
        for (int w = 0; w < 8; w++) s += ws[w][d];
        if (d < 4) g_s1[i * H + d] = s;
        else       g_s2[i * H + (d - 4)] = s;
    }
}

// ---------------- kernel 2: global max of s2 per head ----------------
__global__ void k_gmax() {
    int tid = threadIdx.x;
    float4 m = make_float4(-3.0e38f, -3.0e38f, -3.0e38f, -3.0e38f);
    const float4* s24 = (const float4*)g_s2;
    for (int j = tid; j < N; j += 256) {
        float4 s = s24[j];
        m.x = fmaxf(m.x, s.x); m.y = fmaxf(m.y, s.y);
        m.z = fmaxf(m.z, s.z); m.w = fmaxf(m.w, s.w);
    }
    __shared__ float4 red[256];
    red[tid] = m;
    __syncthreads();
    for (int s = 128; s > 0; s >>= 1) {
        if (tid < s) {
            float4 a_ = red[tid], b = red[tid + s];
            red[tid] = make_float4(fmaxf(a_.x, b.x), fmaxf(a_.y, b.y),
                                   fmaxf(a_.z, b.z), fmaxf(a_.w, b.w));
        }
        __syncthreads();
    }
    if (tid == 0) {
        g_G[0] = red[0].x; g_G[1] = red[0].y;
        g_G[2] = red[0].z; g_G[3] = red[0].w;
    }
}

// ---------------- kernel 3: masked softmax weights, head-folded, bf16 out --
__global__ void k_row(const int* __restrict__ adj) {
    extern __shared__ float sm[];
    float4* wc = (float4*)sm;                        // [N] float4 = 64 KB
    float4* zred = (float4*)(sm + N * 4);            // [256] float4 = 4 KB

    int i = blockIdx.x;
    int tid = threadIdx.x;

    __shared__ float s1v[H], Mv[H], iZ[H];
    if (tid < H) {
        float s1 = g_s1[i * H + tid];
        s1v[tid] = s1;
        Mv[tid] = elu_f(s1 + g_G[tid]);              // >= masked max of e
    }
    __syncthreads();

    float s10 = s1v[0], s11 = s1v[1], s12 = s1v[2], s13 = s1v[3];
    float M0 = Mv[0], M1 = Mv[1], M2 = Mv[2], M3 = Mv[3];

    float Z0 = 0.f, Z1 = 0.f, Z2 = 0.f, Z3 = 0.f;
    const float4* s24 = (const float4*)g_s2;
    const int* arow = adj + (size_t)i * N;

    #pragma unroll 4
    for (int jt = 0; jt < N / 256; jt++) {
        int j = jt * 256 + tid;
        int mask = arow[j];
        float4 s2 = s24[j];
        float w0 = __expf(elu_f(s10 + s2.x) - M0);
        float w1 = __expf(elu_f(s11 + s2.y) - M1);
        float w2 = __expf(elu_f(s12 + s2.z) - M2);
        float w3 = __expf(elu_f(s13 + s2.w) - M3);
        if (mask <= 0) { w0 = 0.f; w1 = 0.f; w2 = 0.f; w3 = 0.f; }
        Z0 += w0; Z1 += w1; Z2 += w2; Z3 += w3;
        wc[j] = make_float4(w0, w1, w2, w3);
    }

    zred[tid] = make_float4(Z0, Z1, Z2, Z3);
    __syncthreads();
    for (int s = 128; s > 0; s >>= 1) {
        if (tid < s) {
            float4 a_ = zred[tid], b = zred[tid + s];
            zred[tid] = make_float4(a_.x + b.x, a_.y + b.y, a_.z + b.z, a_.w + b.w);
        }
        __syncthreads();
    }
    if (tid == 0) {
        float4 z = zred[0];
        iZ[0] = 0.25f / fmaxf(z.x, 1e-30f);
        iZ[1] = 0.25f / fmaxf(z.y, 1e-30f);
        iZ[2] = 0.25f / fmaxf(z.z, 1e-30f);
        iZ[3] = 0.25f / fmaxf(z.w, 1e-30f);
    }
    __syncthreads();

    float i0 = iZ[0], i1 = iZ[1], i2 = iZ[2], i3 = iZ[3];
    __nv_bfloat16* Wrow = g_Wb + (size_t)i * N;
    #pragma unroll 2
    for (int jt = 0; jt < N / 512; jt++) {
        int j = jt * 512 + tid * 2;
        float4 wa = wc[j];
        float4 wb = wc[j + 1];
        float va = wa.x * i0 + wa.y * i1 + wa.z * i2 + wa.w * i3;
        float vb = wb.x * i0 + wb.y * i1 + wb.z * i2 + wb.w * i3;
        __nv_bfloat162 pk;
        pk.x = __float2bfloat16_rn(va);
        pk.y = __float2bfloat16_rn(vb);
        *(__nv_bfloat162*)&Wrow[j] = pk;
    }
}

// ---------------- kernel 4: O = W' @ h  via mma.sync bf16 -----------------
// BM=128, BN=64, BK=64, 256 threads (8 warps: 4 M x 2 N, each 32x32).
#define BM 128
#define BN 64
#define BK 64
#define ABYTES (BM * BK * 2)                // 16384  (128 rows x 128B)
#define BBYTES (BK * BN * 2)                // 8192   (64 rows x 128B)
#define NSTAGE (N / BK)                     // 64

__device__ __forceinline__ void gemm_load(uint32_t aB, uint32_t bB,
                                          int m0, int n0, int k0, int tid) {
    const char* Ap = (const char*)g_Wb;
    const char* Bp = (const char*)g_hb;
    // A: 128 rows x 8 chunks(16B) = 1024 -> 4 per thread
    #pragma unroll
    for (int t = 0; t < 4; t++) {
        int idx = tid + t * 256;
        int row = idx >> 3, ch = (idx & 7) * 16;
        cp_async16(aB + sw128(row * 128 + ch),
                   Ap + ((size_t)(m0 + row) * N + k0) * 2 + ch);
    }
    // B: 64 rows x 8 chunks = 512 -> 2 per thread
    #pragma unroll
    for (int t = 0; t < 2; t++) {
        int idx = tid + t * 256;
        int row = idx >> 3, ch = (idx & 7) * 16;
        cp_async16(bB + sw128(row * 128 + ch),
                   Bp + ((size_t)(k0 + row) * D + n0) * 2 + ch);
    }
}

__global__ void __launch_bounds__(256) k_gemm_mma() {
    extern __shared__ __align__(16) char dsm[];
    uint32_t base = smem_u32(dsm);
    uint32_t aT[2] = { base, base + ABYTES + BBYTES };
    uint32_t bT[2] = { base + ABYTES, base + 2 * ABYTES + BBYTES };

    int tid = threadIdx.x;
    int lane = tid & 31, wid = tid >> 5;
    int wm = (wid & 3) * 32;                 // warp M offset within tile
    int wn = (wid >> 2) * 32;                // warp N offset within tile
    int n0 = blockIdx.x * BN;
    int m0 = blockIdx.y * BM;

    float c[2][4][4];
    #pragma unroll
    for (int mt = 0; mt < 2; mt++)
        #pragma unroll
        for (int nt = 0; nt < 4; nt++)
            #pragma unroll
            for (int q = 0; q < 4; q++) c[mt][nt][q] = 0.f;

    gemm_load(aT[0], bT[0], m0, n0, 0, tid);
    CP_COMMIT();

    int lrow = lane & 15;                    // ldmatrix row select
    int lcol = (lane >> 4) * 16;             // ldmatrix 16B chunk select

    for (int kc = 0; kc < NSTAGE; kc++) {
        int buf = kc & 1;
        if (kc + 1 < NSTAGE) {
            gemm_load(aT[buf ^ 1], bT[buf ^ 1], m0, n0, (kc + 1) * BK, tid);
            CP_COMMIT();
            CP_WAIT(1);
        } else {
            CP_WAIT(0);
        }
        __syncthreads();

        #pragma unroll
        for (int kk = 0; kk < BK; kk += 16) {
            uint32_t a[2][4];
            #pragma unroll
            for (int mt = 0; mt < 2; mt++) {
                uint32_t off = sw128((uint32_t)((wm + mt * 16 + lrow) * 128 + kk * 2 + lcol));
                ldsm_x4(aT[buf] + off, a[mt][0], a[mt][1], a[mt][2], a[mt][3]);
            }
            uint32_t b[4][2];
            #pragma unroll
            for (int nt2 = 0; nt2 < 2; nt2++) {
                uint32_t off = sw128((uint32_t)((kk + lrow) * 128 + (wn + nt2 * 16) * 2 + lcol));
                uint32_t r0, r1, r2, r3;
                ldsm_x4_t(bT[buf] + off, r0, r1, r2, r3);
                b[nt2 * 2][0] = r0; b[nt2 * 2][1] = r1;
                b[nt2 * 2 + 1][0] = r2; b[nt2 * 2 + 1][1] = r3;
            }
            #pragma unroll
            for (int mt = 0; mt < 2; mt++)
                #pragma unroll
                for (int nt = 0; nt < 4; nt++)
                    mma_bf16(c[mt][nt][0], c[mt][nt][1], c[mt][nt][2], c[mt][nt][3],
                             a[mt][0], a[mt][1], a[mt][2], a[mt][3],
                             b[nt][0], b[nt][1]);
        }
        __syncthreads();
    }

    // epilogue
    #pragma unroll
    for (int mt = 0; mt < 2; mt++) {
        int row0 = m0 + wm + mt * 16 + (lane >> 2);
        #pragma unroll
        for (int nt = 0; nt < 4; nt++) {
            int col = n0 + wn + nt * 8 + (lane & 3) * 2;
            *(float2*)&g_O[(size_t)row0 * D + col] = make_float2(c[mt][nt][0], c[mt][nt][1]);
            *(float2*)&g_O[(size_t)(row0 + 8) * D + col] = make_float2(c[mt][nt][2], c[mt][nt][3]);
        }
    }
}

// ---------------- kernel 5: elu(0.5*(O+h)), row-normalize, +bias ----------
__global__ void k_final(const float* __restrict__ bias, float* __restrict__ out) {
    int i = blockIdx.x;
    int d = threadIdx.x;
    float v = 0.5f * (g_O[(size_t)i * D + d] + g_h[(size_t)i * D + d]);
    float u = v > 0.f ? v : expm1f(v);

    __shared__ float red[D];
    red[d] = u * u;
    __syncthreads();
    for (int s = D / 2; s > 0; s >>= 1) {
        if (d < s) red[d] += red[d + s];
        __syncthreads();
    }
    __shared__ float nrm;
    if (d == 0) nrm = fmaxf(sqrtf(red[0]), 1e-12f);
    __syncthreads();
    out[(size_t)i * D + d] = u / nrm + bias[d];
}

// ---------------- launcher ----------------
extern "C" void kernel_launch(void* const* d_in, const int* in_sizes, int n_in,
                              void* d_out, int out_size) {
    const float* x   = (const float*)d_in[0];
    const int*   adj = (const int*)d_in[1];
    const float* cw  = (const float*)d_in[2];
    const float* cb  = (const float*)d_in[3];
    const float* a   = (const float*)d_in[4];
    const float* bias= (const float*)d_in[5];
    float* out = (float*)d_out;

    k_prep<<<N, D>>>(x, cw, cb, a);
    k_gmax<<<1, 256>>>();

    int smem_row = N * 4 * sizeof(float) + 256 * 4 * sizeof(float);  // 69632
    cudaFuncSetAttribute(k_row, cudaFuncAttributeMaxDynamicSharedMemorySize, smem_row);
    k_row<<<N, 256, smem_row>>>(adj);

    int smem_gemm = 2 * (ABYTES + BBYTES);       // 49152
    cudaFuncSetAttribute(k_gemm_mma, cudaFuncAttributeMaxDynamicSharedMemorySize, smem_gemm);
    dim3 grid(D / BN, N / BM);                   // (4, 32) = 128 CTAs
    k_gemm_mma<<<grid, 256, smem_gemm>>>();

    k_final<<<N, D>>>(bias, out);
}

// round 4
// speedup vs baseline: 4.0487x; 1.3970x over previous
#include <cuda_runtime.h>
#include <cuda_bf16.h>
#include <math.h>
#include <cstdint>

// Problem constants
#define N 4096
#define D 256
#define H 4

// ---------------- device scratch ----------------
__device__ float g_h[N * D];                    // h fp32 (4 MB)
__device__ __nv_bfloat16 g_hb[N * D];           // h bf16 row-major (2 MB)  B operand
__device__ float g_s1[N * H];
__device__ float g_s2[N * H];
__device__ unsigned int g_Gu[H];                // encoded global max of s2
__device__ __nv_bfloat16 g_Wb[(size_t)N * N];   // head-folded weights bf16 (32 MB)
__device__ float g_O1[N * D];                   // split-K partial 0 (4 MB)
__device__ float g_O2[N * D];                   // split-K partial 1 (4 MB)

// ---------------- helpers ----------------
__device__ __forceinline__ float elu_f(float x) {
    return x > 0.f ? x : (__expf(x) - 1.f);
}
__device__ __forceinline__ unsigned int enc_f(float f) {
    unsigned int u = __float_as_uint(f);
    return (u & 0x80000000u) ? ~u : (u | 0x80000000u);
}
__device__ __forceinline__ float dec_f(unsigned int u) {
    unsigned int b = (u & 0x80000000u) ? (u & 0x7FFFFFFFu) : ~u;
    return __uint_as_float(b);
}
__device__ __forceinline__ uint32_t smem_u32(const void* p) {
    uint32_t a;
    asm("{ .reg .u64 t; cvta.to.shared.u64 t, %1; cvt.u32.u64 %0, t; }" : "=r"(a) : "l"(p));
    return a;
}
__device__ __forceinline__ uint32_t sw128(uint32_t off) {
    return off ^ ((off >> 3) & 0x70);
}
__device__ __forceinline__ void cp_async16(uint32_t dst, const void* src) {
    asm volatile("cp.async.cg.shared.global [%0], [%1], 16;" :: "r"(dst), "l"(src) : "memory");
}
#define CP_COMMIT() asm volatile("cp.async.commit_group;" ::: "memory")
#define CP_WAIT(n)  asm volatile("cp.async.wait_group %0;" :: "n"(n) : "memory")

__device__ __forceinline__ void ldsm_x4(uint32_t addr, uint32_t& r0, uint32_t& r1,
                                        uint32_t& r2, uint32_t& r3) {
    asm volatile("ldmatrix.sync.aligned.m8n8.x4.shared.b16 {%0,%1,%2,%3}, [%4];"
                 : "=r"(r0), "=r"(r1), "=r"(r2), "=r"(r3) : "r"(addr));
}
__device__ __forceinline__ void ldsm_x4_t(uint32_t addr, uint32_t& r0, uint32_t& r1,
                                          uint32_t& r2, uint32_t& r3) {
    asm volatile("ldmatrix.sync.aligned.m8n8.x4.trans.shared.b16 {%0,%1,%2,%3}, [%4];"
                 : "=r"(r0), "=r"(r1), "=r"(r2), "=r"(r3) : "r"(addr));
}
__device__ __forceinline__ void mma_bf16(float& c0, float& c1, float& c2, float& c3,
                                         uint32_t a0, uint32_t a1, uint32_t a2, uint32_t a3,
                                         uint32_t b0, uint32_t b1) {
    asm volatile("mma.sync.aligned.m16n8k16.row.col.f32.bf16.bf16.f32 "
                 "{%0,%1,%2,%3}, {%4,%5,%6,%7}, {%8,%9}, {%0,%1,%2,%3};"
                 : "+f"(c0), "+f"(c1), "+f"(c2), "+f"(c3)
                 : "r"(a0), "r"(a1), "r"(a2), "r"(a3), "r"(b0), "r"(b1));
}

// ---------------- kernel 0: init global-max accumulators ----------------
__global__ void k_init() {
    if (threadIdx.x < H) g_Gu[threadIdx.x] = 0u;
}

// ---------------- kernel 1: h, hb(bf16), s1, s2, fold global max ----------
__global__ void k_prep(const float* __restrict__ x,
                       const float* __restrict__ cw,
                       const float* __restrict__ cb,
                       const float* __restrict__ a) {
    int i = blockIdx.x;
    int d = threadIdx.x;                     // 256 threads = D
    int lane = d & 31, warp = d >> 5;
    float hv = x[(size_t)i * D + d] * cw[0] + cb[0];
    g_h[(size_t)i * D + d] = hv;
    g_hb[(size_t)i * D + d] = __float2bfloat16_rn(hv);

    float p[8];
    #pragma unroll
    for (int hh = 0; hh < H; hh++) {
        p[hh]     = hv * a[hh * (2 * D) + d];
        p[hh + 4] = hv * a[hh * (2 * D) + D + d];
    }
    #pragma unroll
    for (int s = 16; s > 0; s >>= 1)
        #pragma unroll
        for (int k = 0; k < 8; k++)
            p[k] += __shfl_down_sync(0xFFFFFFFFu, p[k], s);

    __shared__ float ws[8][8];
    if (lane == 0)
        #pragma unroll
        for (int k = 0; k < 8; k++) ws[warp][k] = p[k];
    __syncthreads();
    if (d < 8) {
        float s = 0.f;
        #pragma unroll
        for (int w = 0; w < 8; w++) s += ws[w][d];
        if (d < 4) {
            g_s1[i * H + d] = s;
        } else {
            g_s2[i * H + (d - 4)] = s;
            atomicMax(&g_Gu[d - 4], enc_f(s));
        }
    }
}

// ---------------- kernel 2: masked softmax weights, head-folded, bf16 out --
// One block per row. w cached in smem as bf16 (32 KB) -> 6 CTAs/SM.
__global__ void __launch_bounds__(256) k_row(const int* __restrict__ adj) {
    __shared__ uint2 wc[N];                          // 4 bf16 per j = 32 KB
    __shared__ float zw[8][4];
    __shared__ float s1v[H], Mv[H], iZ[H];

    int i = blockIdx.x;
    int tid = threadIdx.x;
    int lane = tid & 31, warp = tid >> 5;

    if (tid < H) {
        float s1 = g_s1[i * H + tid];
        s1v[tid] = s1;
        Mv[tid] = elu_f(s1 + dec_f(g_Gu[tid]));      // >= masked max of e
    }
    __syncthreads();

    float s10 = s1v[0], s11 = s1v[1], s12 = s1v[2], s13 = s1v[3];
    float M0 = Mv[0], M1 = Mv[1], M2 = Mv[2], M3 = Mv[3];

    float Z0 = 0.f, Z1 = 0.f, Z2 = 0.f, Z3 = 0.f;
    const float4* s24 = (const float4*)g_s2;
    const int4* arow4 = (const int4*)(adj + (size_t)i * N);

    #pragma unroll
    for (int it = 0; it < 4; it++) {
        int jb = it * 1024 + tid * 4;                // 4 consecutive j per thread
        int4 m4 = arow4[jb >> 2];
        float4 sA = s24[jb + 0];
        float4 sB = s24[jb + 1];
        float4 sC = s24[jb + 2];
        float4 sD = s24[jb + 3];

        #pragma unroll
        for (int q = 0; q < 4; q++) {
            float4 s2 = (q == 0) ? sA : (q == 1) ? sB : (q == 2) ? sC : sD;
            int msk = (q == 0) ? m4.x : (q == 1) ? m4.y : (q == 2) ? m4.z : m4.w;
            float w0 = __expf(elu_f(s10 + s2.x) - M0);
            float w1 = __expf(elu_f(s11 + s2.y) - M1);
            float w2 = __expf(elu_f(s12 + s2.z) - M2);
            float w3 = __expf(elu_f(s13 + s2.w) - M3);
            if (msk <= 0) { w0 = 0.f; w1 = 0.f; w2 = 0.f; w3 = 0.f; }
            Z0 += w0; Z1 += w1; Z2 += w2; Z3 += w3;
            __nv_bfloat162 lo = __floats2bfloat162_rn(w0, w1);
            __nv_bfloat162 hi = __floats2bfloat162_rn(w2, w3);
            wc[jb + q] = make_uint2(*(uint32_t*)&lo, *(uint32_t*)&hi);
        }
    }

    // Z reduction: warp shuffle + cross-warp
    #pragma unroll
    for (int s = 16; s > 0; s >>= 1) {
        Z0 += __shfl_down_sync(0xFFFFFFFFu, Z0, s);
        Z1 += __shfl_down_sync(0xFFFFFFFFu, Z1, s);
        Z2 += __shfl_down_sync(0xFFFFFFFFu, Z2, s);
        Z3 += __shfl_down_sync(0xFFFFFFFFu, Z3, s);
    }
    if (lane == 0) { zw[warp][0] = Z0; zw[warp][1] = Z1; zw[warp][2] = Z2; zw[warp][3] = Z3; }
    __syncthreads();
    if (tid < 4) {
        float z = 0.f;
        #pragma unroll
        for (int w = 0; w < 8; w++) z += zw[w][tid];
        iZ[tid] = 0.25f / fmaxf(z, 1e-30f);
    }
    __syncthreads();

    float i0 = iZ[0], i1 = iZ[1], i2 = iZ[2], i3 = iZ[3];
    __nv_bfloat16* Wrow = g_Wb + (size_t)i * N;
    #pragma unroll
    for (int it = 0; it < 4; it++) {
        int jb = it * 1024 + tid * 4;
        float o[4];
        #pragma unroll
        for (int q = 0; q < 4; q++) {
            uint2 pk = wc[jb + q];
            float2 lo = __bfloat1622float2(*(__nv_bfloat162*)&pk.x);
            float2 hi = __bfloat1622float2(*(__nv_bfloat162*)&pk.y);
            o[q] = lo.x * i0 + lo.y * i1 + hi.x * i2 + hi.y * i3;
        }
        __nv_bfloat162 o01 = __floats2bfloat162_rn(o[0], o[1]);
        __nv_bfloat162 o23 = __floats2bfloat162_rn(o[2], o[3]);
        *(uint2*)&Wrow[jb] = make_uint2(*(uint32_t*)&o01, *(uint32_t*)&o23);
    }
}

// ---------------- kernel 3: O = W' @ h  via mma.sync bf16, split-K=2 ------
#define BM 128
#define BN 64
#define BK 64
#define ABYTES (BM * BK * 2)                // 16384
#define BBYTES (BK * BN * 2)                // 8192
#define KSPLIT 2
#define NST (N / BK / KSPLIT)               // 32 stages per CTA

__device__ __forceinline__ void gemm_load(uint32_t aB, uint32_t bB,
                                          int m0, int n0, int k0, int tid) {
    const char* Ap = (const char*)g_Wb;
    const char* Bp = (const char*)g_hb;
    #pragma unroll
    for (int t = 0; t < 4; t++) {
        int idx = tid + t * 256;
        int row = idx >> 3, ch = (idx & 7) * 16;
        cp_async16(aB + sw128(row * 128 + ch),
                   Ap + ((size_t)(m0 + row) * N + k0) * 2 + ch);
    }
    #pragma unroll
    for (int t = 0; t < 2; t++) {
        int idx = tid + t * 256;
        int row = idx >> 3, ch = (idx & 7) * 16;
        cp_async16(bB + sw128(row * 128 + ch),
                   Bp + ((size_t)(k0 + row) * D + n0) * 2 + ch);
    }
}

__global__ void __launch_bounds__(256) k_gemm_mma() {
    extern __shared__ __align__(16) char dsm[];
    uint32_t base = smem_u32(dsm);
    uint32_t aT[3], bT[3];
    #pragma unroll
    for (int s = 0; s < 3; s++) {
        aT[s] = base + s * (ABYTES + BBYTES);
        bT[s] = aT[s] + ABYTES;
    }

    int tid = threadIdx.x;
    int lane = tid & 31, wid = tid >> 5;
    int wm = (wid & 3) * 32;
    int wn = (wid >> 2) * 32;
    int n0 = blockIdx.x * BN;
    int m0 = blockIdx.y * BM;
    int kb = blockIdx.z * (N / KSPLIT);
    float* Oo = blockIdx.z ? g_O2 : g_O1;

    float c[2][4][4];
    #pragma unroll
    for (int mt = 0; mt < 2; mt++)
        #pragma unroll
        for (int nt = 0; nt < 4; nt++)
            #pragma unroll
            for (int q = 0; q < 4; q++) c[mt][nt][q] = 0.f;

    gemm_load(aT[0], bT[0], m0, n0, kb, tid);
    CP_COMMIT();
    gemm_load(aT[1], bT[1], m0, n0, kb + BK, tid);
    CP_COMMIT();

    int lrow = lane & 15;
    int lcol = (lane >> 4) * 16;

    for (int kc = 0; kc < NST; kc++) {
        int buf = kc % 3;
        if (kc + 1 < NST) { CP_WAIT(1); } else { CP_WAIT(0); }
        __syncthreads();
        if (kc + 2 < NST) {
            gemm_load(aT[(kc + 2) % 3], bT[(kc + 2) % 3], m0, n0, kb + (kc + 2) * BK, tid);
            CP_COMMIT();
        }

        #pragma unroll
        for (int kk = 0; kk < BK; kk += 16) {
            uint32_t a[2][4];
            #pragma unroll
            for (int mt = 0; mt < 2; mt++) {
                uint32_t off = sw128((uint32_t)((wm + mt * 16 + lrow) * 128 + kk * 2 + lcol));
                ldsm_x4(aT[buf] + off, a[mt][0], a[mt][1], a[mt][2], a[mt][3]);
            }
            uint32_t b[4][2];
            #pragma unroll
            for (int nt2 = 0; nt2 < 2; nt2++) {
                uint32_t off = sw128((uint32_t)((kk + lrow) * 128 + (wn + nt2 * 16) * 2 + lcol));
                uint32_t r0, r1, r2, r3;
                ldsm_x4_t(bT[buf] + off, r0, r1, r2, r3);
                b[nt2 * 2][0] = r0; b[nt2 * 2][1] = r1;
                b[nt2 * 2 + 1][0] = r2; b[nt2 * 2 + 1][1] = r3;
            }
            #pragma unroll
            for (int mt = 0; mt < 2; mt++)
                #pragma unroll
                for (int nt = 0; nt < 4; nt++)
                    mma_bf16(c[mt][nt][0], c[mt][nt][1], c[mt][nt][2], c[mt][nt][3],
                             a[mt][0], a[mt][1], a[mt][2], a[mt][3],
                             b[nt][0], b[nt][1]);
        }
    }

    #pragma unroll
    for (int mt = 0; mt < 2; mt++) {
        int row0 = m0 + wm + mt * 16 + (lane >> 2);
        #pragma unroll
        for (int nt = 0; nt < 4; nt++) {
            int col = n0 + wn + nt * 8 + (lane & 3) * 2;
            *(float2*)&Oo[(size_t)row0 * D + col] = make_float2(c[mt][nt][0], c[mt][nt][1]);
            *(float2*)&Oo[(size_t)(row0 + 8) * D + col] = make_float2(c[mt][nt][2], c[mt][nt][3]);
        }
    }
}

// ---------------- kernel 4: elu(0.5*(O1+O2+h)), row-normalize, +bias ------
__global__ void __launch_bounds__(256) k_final(const float* __restrict__ bias,
                                               float* __restrict__ out) {
    int i = blockIdx.x;
    int d = threadIdx.x;
    int lane = d & 31, warp = d >> 5;
    size_t idx = (size_t)i * D + d;
    float v = 0.5f * (g_O1[idx] + g_O2[idx] + g_h[idx]);
    float u = v > 0.f ? v : expm1f(v);

    float ss = u * u;
    #pragma unroll
    for (int s = 16; s > 0; s >>= 1) ss += __shfl_down_sync(0xFFFFFFFFu, ss, s);
    __shared__ float rw[8];
    if (lane == 0) rw[warp] = ss;
    __syncthreads();
    __shared__ float nrm;
    if (d == 0) {
        float t = 0.f;
        #pragma unroll
        for (int w = 0; w < 8; w++) t += rw[w];
        nrm = fmaxf(sqrtf(t), 1e-12f);
    }
    __syncthreads();
    out[idx] = u / nrm + bias[d];
}

// ---------------- launcher ----------------
extern "C" void kernel_launch(void* const* d_in, const int* in_sizes, int n_in,
                              void* d_out, int out_size) {
    const float* x   = (const float*)d_in[0];
    const int*   adj = (const int*)d_in[1];
    const float* cw  = (const float*)d_in[2];
    const float* cb  = (const float*)d_in[3];
    const float* a   = (const float*)d_in[4];
    const float* bias= (const float*)d_in[5];
    float* out = (float*)d_out;

    k_init<<<1, 32>>>();
    k_prep<<<N, D>>>(x, cw, cb, a);
    k_row<<<N, 256>>>(adj);

    int smem_gemm = 3 * (ABYTES + BBYTES);       // 73728
    cudaFuncSetAttribute(k_gemm_mma, cudaFuncAttributeMaxDynamicSharedMemorySize, smem_gemm);
    dim3 grid(D / BN, N / BM, KSPLIT);           // (4, 32, 2) = 256 CTAs
    k_gemm_mma<<<grid, 256, smem_gemm>>>();

    k_final<<<N, D>>>(bias, out);
}

// round 5
// speedup vs baseline: 4.4885x; 1.1086x over previous
#include <cuda_runtime.h>
#include <cuda_bf16.h>
#include <math.h>
#include <cstdint>

// Problem constants
#define N 4096
#define D 256
#define H 4
#define LOG2E 1.4426950408889634f

// ---------------- device scratch ----------------
__device__ float g_h[N * D];                    // h fp32 (4 MB)
__device__ __nv_bfloat16 g_hb[N * D];           // h bf16 row-major (2 MB)
__device__ float g_s1[N * H];
__device__ float g_s2L[N * H];                  // s2 * log2e
__device__ unsigned int g_Gu[H];                // encoded global max of s2 (raw)
__device__ __nv_bfloat16 g_Wb[(size_t)N * N];   // head-folded weights bf16 (32 MB)
__device__ float g_O1[N * D];                   // split-K partial 0
__device__ float g_O2[N * D];                   // split-K partial 1

// ---------------- helpers ----------------
__device__ __forceinline__ float elu_f(float x) {
    return x > 0.f ? x : (__expf(x) - 1.f);
}
__device__ __forceinline__ float ex2f(float x) {
    float r;
    asm("ex2.approx.ftz.f32 %0, %1;" : "=f"(r) : "f"(x));
    return r;
}
__device__ __forceinline__ unsigned int enc_f(float f) {
    unsigned int u = __float_as_uint(f);
    return (u & 0x80000000u) ? ~u : (u | 0x80000000u);
}
__device__ __forceinline__ float dec_f(unsigned int u) {
    unsigned int b = (u & 0x80000000u) ? (u & 0x7FFFFFFFu) : ~u;
    return __uint_as_float(b);
}
__device__ __forceinline__ uint32_t smem_u32(const void* p) {
    uint32_t a;
    asm("{ .reg .u64 t; cvta.to.shared.u64 t, %1; cvt.u32.u64 %0, t; }" : "=r"(a) : "l"(p));
    return a;
}
__device__ __forceinline__ uint32_t sw128(uint32_t off) {
    return off ^ ((off >> 3) & 0x70);
}
__device__ __forceinline__ void cp_async16(uint32_t dst, const void* src) {
    asm volatile("cp.async.cg.shared.global [%0], [%1], 16;" :: "r"(dst), "l"(src) : "memory");
}
#define CP_COMMIT() asm volatile("cp.async.commit_group;" ::: "memory")
#define CP_WAIT(n)  asm volatile("cp.async.wait_group %0;" :: "n"(n) : "memory")

__device__ __forceinline__ void ldsm_x4(uint32_t addr, uint32_t* r) {
    asm volatile("ldmatrix.sync.aligned.m8n8.x4.shared.b16 {%0,%1,%2,%3}, [%4];"
                 : "=r"(r[0]), "=r"(r[1]), "=r"(r[2]), "=r"(r[3]) : "r"(addr));
}
__device__ __forceinline__ void ldsm_x4_t(uint32_t addr, uint32_t* r) {
    asm volatile("ldmatrix.sync.aligned.m8n8.x4.trans.shared.b16 {%0,%1,%2,%3}, [%4];"
                 : "=r"(r[0]), "=r"(r[1]), "=r"(r[2]), "=r"(r[3]) : "r"(addr));
}
__device__ __forceinline__ void mma_bf16(float* c, const uint32_t* a, const uint32_t* b) {
    asm volatile("mma.sync.aligned.m16n8k16.row.col.f32.bf16.bf16.f32 "
                 "{%0,%1,%2,%3}, {%4,%5,%6,%7}, {%8,%9}, {%0,%1,%2,%3};"
                 : "+f"(c[0]), "+f"(c[1]), "+f"(c[2]), "+f"(c[3])
                 : "r"(a[0]), "r"(a[1]), "r"(a[2]), "r"(a[3]), "r"(b[0]), "r"(b[1]));
}

// ---------------- kernel 0: init global-max accumulators ----------------
__global__ void k_init() {
    if (threadIdx.x < H) g_Gu[threadIdx.x] = 0u;
}

// ---------------- kernel 1: h, hb(bf16), s1, s2L, global max --------------
__global__ void k_prep(const float* __restrict__ x,
                       const float* __restrict__ cw,
                       const float* __restrict__ cb,
                       const float* __restrict__ a) {
    int i = blockIdx.x;
    int d = threadIdx.x;                     // 256 threads = D
    int lane = d & 31, warp = d >> 5;
    float hv = x[(size_t)i * D + d] * cw[0] + cb[0];
    g_h[(size_t)i * D + d] = hv;
    g_hb[(size_t)i * D + d] = __float2bfloat16_rn(hv);

    float p[8];
    #pragma unroll
    for (int hh = 0; hh < H; hh++) {
        p[hh]     = hv * a[hh * (2 * D) + d];
        p[hh + 4] = hv * a[hh * (2 * D) + D + d];
    }
    #pragma unroll
    for (int s = 16; s > 0; s >>= 1)
        #pragma unroll
        for (int k = 0; k < 8; k++)
            p[k] += __shfl_down_sync(0xFFFFFFFFu, p[k], s);

    __shared__ float ws[8][8];
    if (lane == 0)
        #pragma unroll
        for (int k = 0; k < 8; k++) ws[warp][k] = p[k];
    __syncthreads();
    if (d < 8) {
        float s = 0.f;
        #pragma unroll
        for (int w = 0; w < 8; w++) s += ws[w][d];
        if (d < 4) {
            g_s1[i * H + d] = s;
        } else {
            g_s2L[i * H + (d - 4)] = s * LOG2E;
            atomicMax(&g_Gu[d - 4], enc_f(s));
        }
    }
}

// ---------------- kernel 2: masked softmax weights, head-folded, bf16 out --
// Log2-domain: w = ex2( max(tL + cA, u*L + cB) ), u = ex2(min(tL,0)),
// tL = (s1+s2)*log2e, cA = -M*L, cB = (-1-M)*L, M = elu(s1+G).
__global__ void __launch_bounds__(256) k_row(const int* __restrict__ adj) {
    __shared__ uint2 wc[N];                          // 4 bf16 per j = 32 KB
    __shared__ float zw[8][4];
    __shared__ float iZs[H];

    int i = blockIdx.x;
    int tid = threadIdx.x;
    int lane = tid & 31, warp = tid >> 5;

    float s1L[H], cA[H], cB[H];
    #pragma unroll
    for (int hh = 0; hh < H; hh++) {
        float s1 = g_s1[i * H + hh];
        float M  = elu_f(s1 + dec_f(g_Gu[hh]));
        s1L[hh] = s1 * LOG2E;
        cA[hh]  = -M * LOG2E;
        cB[hh]  = (-1.f - M) * LOG2E;
    }

    float Z0 = 0.f, Z1 = 0.f, Z2 = 0.f, Z3 = 0.f;
    const float4* s2L4 = (const float4*)g_s2L;
    const int4* arow4 = (const int4*)(adj + (size_t)i * N);

    #pragma unroll
    for (int it = 0; it < 4; it++) {
        int jb = it * 1024 + tid * 4;
        int4 m4 = arow4[jb >> 2];
        #pragma unroll
        for (int q = 0; q < 4; q++) {
            float4 s2 = s2L4[jb + q];
            int msk = (q == 0) ? m4.x : (q == 1) ? m4.y : (q == 2) ? m4.z : m4.w;
            float w[4];
            float tl[4] = { s1L[0] + s2.x, s1L[1] + s2.y, s1L[2] + s2.z, s1L[3] + s2.w };
            #pragma unroll
            for (int hh = 0; hh < 4; hh++) {
                float u  = ex2f(fminf(tl[hh], 0.f));
                float yl = fmaxf(tl[hh] + cA[hh], fmaf(u, LOG2E, cB[hh]));
                w[hh] = ex2f(yl);
                if (msk <= 0) w[hh] = 0.f;
            }
            Z0 += w[0]; Z1 += w[1]; Z2 += w[2]; Z3 += w[3];
            __nv_bfloat162 lo = __floats2bfloat162_rn(w[0], w[1]);
            __nv_bfloat162 hi = __floats2bfloat162_rn(w[2], w[3]);
            wc[jb + q] = make_uint2(*(uint32_t*)&lo, *(uint32_t*)&hi);
        }
    }

    #pragma unroll
    for (int s = 16; s > 0; s >>= 1) {
        Z0 += __shfl_down_sync(0xFFFFFFFFu, Z0, s);
        Z1 += __shfl_down_sync(0xFFFFFFFFu, Z1, s);
        Z2 += __shfl_down_sync(0xFFFFFFFFu, Z2, s);
        Z3 += __shfl_down_sync(0xFFFFFFFFu, Z3, s);
    }
    if (lane == 0) { zw[warp][0] = Z0; zw[warp][1] = Z1; zw[warp][2] = Z2; zw[warp][3] = Z3; }
    __syncthreads();
    if (tid < 4) {
        float z = 0.f;
        #pragma unroll
        for (int w = 0; w < 8; w++) z += zw[w][tid];
        iZs[tid] = 0.25f / fmaxf(z, 1e-30f);
    }
    __syncthreads();

    float i0 = iZs[0], i1 = iZs[1], i2 = iZs[2], i3 = iZs[3];
    __nv_bfloat16* Wrow = g_Wb + (size_t)i * N;
    #pragma unroll
    for (int it = 0; it < 4; it++) {
        int jb = it * 1024 + tid * 4;
        float o[4];
        #pragma unroll
        for (int q = 0; q < 4; q++) {
            uint2 pk = wc[jb + q];
            float2 lo = __bfloat1622float2(*(__nv_bfloat162*)&pk.x);
            float2 hi = __bfloat1622float2(*(__nv_bfloat162*)&pk.y);
            o[q] = lo.x * i0 + lo.y * i1 + hi.x * i2 + hi.y * i3;
        }
        __nv_bfloat162 o01 = __floats2bfloat162_rn(o[0], o[1]);
        __nv_bfloat162 o23 = __floats2bfloat162_rn(o[2], o[3]);
        *(uint2*)&Wrow[jb] = make_uint2(*(uint32_t*)&o01, *(uint32_t*)&o23);
    }
}

// ---------------- kernel 3: O = W' @ h  via mma.sync bf16, split-K=2 ------
#define BM 128
#define BN 64
#define BK 64
#define ABYTES (BM * BK * 2)                // 16384
#define BBYTES (BK * BN * 2)                // 8192
#define KSPLIT 2
#define NST (N / BK / KSPLIT)               // 32 stages per CTA

__device__ __forceinline__ void gemm_load(uint32_t aB, uint32_t bB,
                                          int m0, int n0, int k0, int tid) {
    const char* Ap = (const char*)g_Wb;
    const char* Bp = (const char*)g_hb;
    #pragma unroll
    for (int t = 0; t < 4; t++) {
        int idx = tid + t * 256;
        int row = idx >> 3, ch = (idx & 7) * 16;
        cp_async16(aB + sw128(row * 128 + ch),
                   Ap + ((size_t)(m0 + row) * N + k0) * 2 + ch);
    }
    #pragma unroll
    for (int t = 0; t < 2; t++) {
        int idx = tid + t * 256;
        int row = idx >> 3, ch = (idx & 7) * 16;
        cp_async16(bB + sw128(row * 128 + ch),
                   Bp + ((size_t)(k0 + row) * D + n0) * 2 + ch);
    }
}

__global__ void __launch_bounds__(256) k_gemm_mma() {
    extern __shared__ __align__(16) char dsm[];
    uint32_t base = smem_u32(dsm);
    uint32_t aT[3], bT[3];
    #pragma unroll
    for (int s = 0; s < 3; s++) {
        aT[s] = base + s * (ABYTES + BBYTES);
        bT[s] = aT[s] + ABYTES;
    }

    int tid = threadIdx.x;
    int lane = tid & 31, wid = tid >> 5;
    int wm = (wid & 3) * 32;
    int wn = (wid >> 2) * 32;
    int n0 = blockIdx.x * BN;
    int m0 = blockIdx.y * BM;
    int kb = blockIdx.z * (N / KSPLIT);
    float* Oo = blockIdx.z ? g_O2 : g_O1;

    int lrow = lane & 15;
    int lcol = (lane >> 4) * 16;
    // swizzled base offsets (kk-varying bits proven carry-free: A ^ (kk<<1), B + (kk<<7))
    uint32_t swzA[2], swzB[2];
    #pragma unroll
    for (int mt = 0; mt < 2; mt++)
        swzA[mt] = sw128((uint32_t)((wm + mt * 16 + lrow) * 128 + lcol));
    #pragma unroll
    for (int nt2 = 0; nt2 < 2; nt2++)
        swzB[nt2] = sw128((uint32_t)(lrow * 128 + (wn + nt2 * 16) * 2 + lcol));

    float c[2][4][4];
    #pragma unroll
    for (int mt = 0; mt < 2; mt++)
        #pragma unroll
        for (int nt = 0; nt < 4; nt++)
            #pragma unroll
            for (int q = 0; q < 4; q++) c[mt][nt][q] = 0.f;

    gemm_load(aT[0], bT[0], m0, n0, kb, tid);
    CP_COMMIT();
    gemm_load(aT[1], bT[1], m0, n0, kb + BK, tid);
    CP_COMMIT();

    for (int kc = 0; kc < NST; kc++) {
        int buf = kc % 3;
        if (kc + 1 < NST) { CP_WAIT(1); } else { CP_WAIT(0); }
        __syncthreads();
        if (kc + 2 < NST) {
            gemm_load(aT[(kc + 2) % 3], bT[(kc + 2) % 3], m0, n0, kb + (kc + 2) * BK, tid);
            CP_COMMIT();
        }

        uint32_t afr[2][2][4], bfr[2][4][2];
        uint32_t aTb = aT[buf], bTb = bT[buf];

        // prefetch kk=0 fragments
        #pragma unroll
        for (int mt = 0; mt < 2; mt++)
            ldsm_x4(aTb + swzA[mt], afr[0][mt]);
        #pragma unroll
        for (int nt2 = 0; nt2 < 2; nt2++) {
            uint32_t r[4];
            ldsm_x4_t(bTb + swzB[nt2], r);
            bfr[0][nt2 * 2][0] = r[0]; bfr[0][nt2 * 2][1] = r[1];
            bfr[0][nt2 * 2 + 1][0] = r[2]; bfr[0][nt2 * 2 + 1][1] = r[3];
        }

        #pragma unroll
        for (int ks = 0; ks < 4; ks++) {
            int cur = ks & 1, nxt = cur ^ 1;
            if (ks < 3) {
                int kk = (ks + 1) * 16;
                #pragma unroll
                for (int mt = 0; mt < 2; mt++)
                    ldsm_x4(aTb + (swzA[mt] ^ (uint32_t)(kk << 1)), afr[nxt][mt]);
                #pragma unroll
                for (int nt2 = 0; nt2 < 2; nt2++) {
                    uint32_t r[4];
                    ldsm_x4_t(bTb + swzB[nt2] + (uint32_t)(kk << 7), r);
                    bfr[nxt][nt2 * 2][0] = r[0]; bfr[nxt][nt2 * 2][1] = r[1];
                    bfr[nxt][nt2 * 2 + 1][0] = r[2]; bfr[nxt][nt2 * 2 + 1][1] = r[3];
                }
            }
            #pragma unroll
            for (int mt = 0; mt < 2; mt++)
                #pragma unroll
                for (int nt = 0; nt < 4; nt++)
                    mma_bf16(c[mt][nt], afr[cur][mt], bfr[cur][nt]);
        }
        __syncthreads();
    }

    #pragma unroll
    for (int mt = 0; mt < 2; mt++) {
        int row0 = m0 + wm + mt * 16 + (lane >> 2);
        #pragma unroll
        for (int nt = 0; nt < 4; nt++) {
            int col = n0 + wn + nt * 8 + (lane & 3) * 2;
            *(float2*)&Oo[(size_t)row0 * D + col] = make_float2(c[mt][nt][0], c[mt][nt][1]);
            *(float2*)&Oo[(size_t)(row0 + 8) * D + col] = make_float2(c[mt][nt][2], c[mt][nt][3]);
        }
    }
}

// ---------------- kernel 4: elu(0.5*(O1+O2+h)), row-normalize, +bias ------
__global__ void __launch_bounds__(256) k_final(const float* __restrict__ bias,
                                               float* __restrict__ out) {
    int i = blockIdx.x;
    int d = threadIdx.x;
    int lane = d & 31, warp = d >> 5;
    size_t idx = (size_t)i * D + d;
    float v = 0.5f * (g_O1[idx] + g_O2[idx] + g_h[idx]);
    float u = v > 0.f ? v : expm1f(v);

    float ss = u * u;
    #pragma unroll
    for (int s = 16; s > 0; s >>= 1) ss += __shfl_down_sync(0xFFFFFFFFu, ss, s);
    __shared__ float rw[8];
    if (lane == 0) rw[warp] = ss;
    __syncthreads();
    __shared__ float nrm;
    if (d == 0) {
        float t = 0.f;
        #pragma unroll
        for (int w = 0; w < 8; w++) t += rw[w];
        nrm = fmaxf(sqrtf(t), 1e-12f);
    }
    __syncthreads();
    out[idx] = u / nrm + bias[d];
}

// ---------------- launcher ----------------
extern "C" void kernel_launch(void* const* d_in, const int* in_sizes, int n_in,
                              void* d_out, int out_size) {
    const float* x   = (const float*)d_in[0];
    const int*   adj = (const int*)d_in[1];
    const float* cw  = (const float*)d_in[2];
    const float* cb  = (const float*)d_in[3];
    const float* a   = (const float*)d_in[4];
    const float* bias= (const float*)d_in[5];
    float* out = (float*)d_out;

    k_init<<<1, 32>>>();
    k_prep<<<N, D>>>(x, cw, cb, a);
    k_row<<<N, 256>>>(adj);

    int smem_gemm = 3 * (ABYTES + BBYTES);       // 73728
    cudaFuncSetAttribute(k_gemm_mma, cudaFuncAttributeMaxDynamicSharedMemorySize, smem_gemm);
    dim3 grid(D / BN, N / BM, KSPLIT);           // (4, 32, 2) = 256 CTAs
    k_gemm_mma<<<grid, 256, smem_gemm>>>();

    k_final<<<N, D>>>(bias, out);
}

// round 6
// speedup vs baseline: 4.5857x; 1.0216x over previous
#include <cuda_runtime.h>
#include <cuda_bf16.h>
#include <math.h>
#include <cstdint>

// Problem constants
#define N 4096
#define D 256
#define H 4
#define LOG2E 1.4426950408889634f

// ---------------- device scratch ----------------
__device__ float g_h[N * D];                    // h fp32 (4 MB)
__device__ __nv_bfloat16 g_hb[N * D];           // h bf16 row-major (2 MB)
__device__ float g_s1L[N * H];                  // s1 * log2e
__device__ float g_s2L[N * H];                  // s2 * log2e
__device__ __nv_bfloat16 g_Wb[(size_t)N * N];   // head-folded weights bf16 (32 MB)
#define KSPLIT 4
__device__ float g_Op[KSPLIT * N * D];          // split-K partials (16 MB)

// Chebyshev coefficients for e^{u-1} on u in [0,1], x = 2u-1 (max rel err ~3e-5)
#define P0 0.6065308f
#define P1 0.3032159f
#define P2 0.0758088f
#define P3 0.0128346f
#define P4 0.0015992f

// ---------------- helpers ----------------
__device__ __forceinline__ float ex2f(float x) {
    float r;
    asm("ex2.approx.ftz.f32 %0, %1;" : "=f"(r) : "f"(x));
    return r;
}
__device__ __forceinline__ uint32_t smem_u32(const void* p) {
    uint32_t a;
    asm("{ .reg .u64 t; cvta.to.shared.u64 t, %1; cvt.u32.u64 %0, t; }" : "=r"(a) : "l"(p));
    return a;
}
__device__ __forceinline__ uint32_t sw128(uint32_t off) {
    return off ^ ((off >> 3) & 0x70);
}
__device__ __forceinline__ void cp_async16(uint32_t dst, const void* src) {
    asm volatile("cp.async.cg.shared.global [%0], [%1], 16;" :: "r"(dst), "l"(src) : "memory");
}
#define CP_COMMIT() asm volatile("cp.async.commit_group;" ::: "memory")
#define CP_WAIT(n)  asm volatile("cp.async.wait_group %0;" :: "n"(n) : "memory")

__device__ __forceinline__ void ldsm_x4(uint32_t addr, uint32_t* r) {
    asm volatile("ldmatrix.sync.aligned.m8n8.x4.shared.b16 {%0,%1,%2,%3}, [%4];"
                 : "=r"(r[0]), "=r"(r[1]), "=r"(r[2]), "=r"(r[3]) : "r"(addr));
}
__device__ __forceinline__ void ldsm_x4_t(uint32_t addr, uint32_t* r) {
    asm volatile("ldmatrix.sync.aligned.m8n8.x4.trans.shared.b16 {%0,%1,%2,%3}, [%4];"
                 : "=r"(r[0]), "=r"(r[1]), "=r"(r[2]), "=r"(r[3]) : "r"(addr));
}
__device__ __forceinline__ void mma_bf16(float* c, const uint32_t* a, const uint32_t* b) {
    asm volatile("mma.sync.aligned.m16n8k16.row.col.f32.bf16.bf16.f32 "
                 "{%0,%1,%2,%3}, {%4,%5,%6,%7}, {%8,%9}, {%0,%1,%2,%3};"
                 : "+f"(c[0]), "+f"(c[1]), "+f"(c[2]), "+f"(c[3])
                 : "r"(a[0]), "r"(a[1]), "r"(a[2]), "r"(a[3]), "r"(b[0]), "r"(b[1]));
}

// ---------------- kernel 1: h, hb(bf16), s1L, s2L --------------------------
__global__ void k_prep(const float* __restrict__ x,
                       const float* __restrict__ cw,
                       const float* __restrict__ cb,
                       const float* __restrict__ a) {
    int i = blockIdx.x;
    int d = threadIdx.x;                     // 256 threads = D
    int lane = d & 31, warp = d >> 5;
    float hv = x[(size_t)i * D + d] * cw[0] + cb[0];
    g_h[(size_t)i * D + d] = hv;
    g_hb[(size_t)i * D + d] = __float2bfloat16_rn(hv);

    float p[8];
    #pragma unroll
    for (int hh = 0; hh < H; hh++) {
        p[hh]     = hv * a[hh * (2 * D) + d];
        p[hh + 4] = hv * a[hh * (2 * D) + D + d];
    }
    #pragma unroll
    for (int s = 16; s > 0; s >>= 1)
        #pragma unroll
        for (int k = 0; k < 8; k++)
            p[k] += __shfl_down_sync(0xFFFFFFFFu, p[k], s);

    __shared__ float ws[8][8];
    if (lane == 0)
        #pragma unroll
        for (int k = 0; k < 8; k++) ws[warp][k] = p[k];
    __syncthreads();
    if (d < 8) {
        float s = 0.f;
        #pragma unroll
        for (int w = 0; w < 8; w++) s += ws[w][d];
        if (d < 4) g_s1L[i * H + d] = s * LOG2E;
        else       g_s2L[i * H + (d - 4)] = s * LOG2E;
    }
}

// ---------------- kernel 2: masked softmax weights, head-folded, bf16 out --
// Shift-free: w = exp(elu(t)) = (u>1) ? u : cheb4(u), u = ex2((s1+s2)*log2e).
__global__ void __launch_bounds__(256) k_row(const int* __restrict__ adj) {
    __shared__ uint2 wc[N];                          // 4 bf16 per j = 32 KB
    __shared__ float zw[8][4];
    __shared__ float iZs[H];

    int i = blockIdx.x;
    int tid = threadIdx.x;
    int lane = tid & 31, warp = tid >> 5;

    float s1L0 = g_s1L[i * H + 0];
    float s1L1 = g_s1L[i * H + 1];
    float s1L2 = g_s1L[i * H + 2];
    float s1L3 = g_s1L[i * H + 3];

    float Z0 = 0.f, Z1 = 0.f, Z2 = 0.f, Z3 = 0.f;
    const float4* s2L4 = (const float4*)g_s2L;
    const int4* arow4 = (const int4*)(adj + (size_t)i * N);

    #pragma unroll
    for (int it = 0; it < 4; it++) {
        int jb = it * 1024 + tid * 4;
        int4 m4 = arow4[jb >> 2];
        #pragma unroll
        for (int q = 0; q < 4; q++) {
            float4 s2 = s2L4[jb + q];
            int msk = (q == 0) ? m4.x : (q == 1) ? m4.y : (q == 2) ? m4.z : m4.w;
            float tl[4] = { s1L0 + s2.x, s1L1 + s2.y, s1L2 + s2.z, s1L3 + s2.w };
            float w[4];
            #pragma unroll
            for (int hh = 0; hh < 4; hh++) {
                float u = ex2f(tl[hh]);
                float xx = fmaf(2.f, u, -1.f);
                float pp = fmaf(P4, xx, P3);
                pp = fmaf(pp, xx, P2);
                pp = fmaf(pp, xx, P1);
                pp = fmaf(pp, xx, P0);
                w[hh] = (u > 1.f) ? u : pp;
                if (msk <= 0) w[hh] = 0.f;
            }
            Z0 += w[0]; Z1 += w[1]; Z2 += w[2]; Z3 += w[3];
            __nv_bfloat162 lo = __floats2bfloat162_rn(w[0], w[1]);
            __nv_bfloat162 hi = __floats2bfloat162_rn(w[2], w[3]);
            wc[jb + q] = make_uint2(*(uint32_t*)&lo, *(uint32_t*)&hi);
        }
    }

    #pragma unroll
    for (int s = 16; s > 0; s >>= 1) {
        Z0 += __shfl_down_sync(0xFFFFFFFFu, Z0, s);
        Z1 += __shfl_down_sync(0xFFFFFFFFu, Z1, s);
        Z2 += __shfl_down_sync(0xFFFFFFFFu, Z2, s);
        Z3 += __shfl_down_sync(0xFFFFFFFFu, Z3, s);
    }
    if (lane == 0) { zw[warp][0] = Z0; zw[warp][1] = Z1; zw[warp][2] = Z2; zw[warp][3] = Z3; }
    __syncthreads();
    if (tid < 4) {
        float z = 0.f;
        #pragma unroll
        for (int w = 0; w < 8; w++) z += zw[w][tid];
        iZs[tid] = 0.25f / fmaxf(z, 1e-30f);
    }
    __syncthreads();

    float i0 = iZs[0], i1 = iZs[1], i2 = iZs[2], i3 = iZs[3];
    __nv_bfloat16* Wrow = g_Wb + (size_t)i * N;
    #pragma unroll
    for (int it = 0; it < 4; it++) {
        int jb = it * 1024 + tid * 4;
        float o[4];
        #pragma unroll
        for (int q = 0; q < 4; q++) {
            uint2 pk = wc[jb + q];
            float2 lo = __bfloat1622float2(*(__nv_bfloat162*)&pk.x);
            float2 hi = __bfloat1622float2(*(__nv_bfloat162*)&pk.y);
            o[q] = lo.x * i0 + lo.y * i1 + hi.x * i2 + hi.y * i3;
        }
        __nv_bfloat162 o01 = __floats2bfloat162_rn(o[0], o[1]);
        __nv_bfloat162 o23 = __floats2bfloat162_rn(o[2], o[3]);
        *(uint2*)&Wrow[jb] = make_uint2(*(uint32_t*)&o01, *(uint32_t*)&o23);
    }
}

// ---------------- kernel 3: O = W' @ h  via mma.sync bf16, split-K=4 ------
#define BM 128
#define BN 64
#define BK 64
#define ABYTES (BM * BK * 2)                // 16384
#define BBYTES (BK * BN * 2)                // 8192
#define NST (N / BK / KSPLIT)               // 16 stages per CTA

__device__ __forceinline__ void gemm_load(uint32_t aB, uint32_t bB,
                                          int m0, int n0, int k0, int tid) {
    const char* Ap = (const char*)g_Wb;
    const char* Bp = (const char*)g_hb;
    #pragma unroll
    for (int t = 0; t < 4; t++) {
        int idx = tid + t * 256;
        int row = idx >> 3, ch = (idx & 7) * 16;
        cp_async16(aB + sw128(row * 128 + ch),
                   Ap + ((size_t)(m0 + row) * N + k0) * 2 + ch);
    }
    #pragma unroll
    for (int t = 0; t < 2; t++) {
        int idx = tid + t * 256;
        int row = idx >> 3, ch = (idx & 7) * 16;
        cp_async16(bB + sw128(row * 128 + ch),
                   Bp + ((size_t)(k0 + row) * D + n0) * 2 + ch);
    }
}

__global__ void __launch_bounds__(256) k_gemm_mma() {
    extern __shared__ __align__(16) char dsm[];
    uint32_t base = smem_u32(dsm);
    uint32_t aT[3], bT[3];
    #pragma unroll
    for (int s = 0; s < 3; s++) {
        aT[s] = base + s * (ABYTES + BBYTES);
        bT[s] = aT[s] + ABYTES;
    }

    int tid = threadIdx.x;
    int lane = tid & 31, wid = tid >> 5;
    int wm = (wid & 3) * 32;
    int wn = (wid >> 2) * 32;
    int n0 = blockIdx.x * BN;
    int m0 = blockIdx.y * BM;
    int kb = blockIdx.z * (N / KSPLIT);
    float* Oo = g_Op + (size_t)blockIdx.z * N * D;

    int lrow = lane & 15;
    int lcol = (lane >> 4) * 16;
    uint32_t swzA[2], swzB[2];
    #pragma unroll
    for (int mt = 0; mt < 2; mt++)
        swzA[mt] = sw128((uint32_t)((wm + mt * 16 + lrow) * 128 + lcol));
    #pragma unroll
    for (int nt2 = 0; nt2 < 2; nt2++)
        swzB[nt2] = sw128((uint32_t)(lrow * 128 + (wn + nt2 * 16) * 2 + lcol));

    float c[2][4][4];
    #pragma unroll
    for (int mt = 0; mt < 2; mt++)
        #pragma unroll
        for (int nt = 0; nt < 4; nt++)
            #pragma unroll
            for (int q = 0; q < 4; q++) c[mt][nt][q] = 0.f;

    gemm_load(aT[0], bT[0], m0, n0, kb, tid);
    CP_COMMIT();
    gemm_load(aT[1], bT[1], m0, n0, kb + BK, tid);
    CP_COMMIT();

    for (int kc = 0; kc < NST; kc++) {
        int buf = kc % 3;
        if (kc + 1 < NST) { CP_WAIT(1); } else { CP_WAIT(0); }
        __syncthreads();
        if (kc + 2 < NST) {
            gemm_load(aT[(kc + 2) % 3], bT[(kc + 2) % 3], m0, n0, kb + (kc + 2) * BK, tid);
            CP_COMMIT();
        }

        uint32_t afr[2][2][4], bfr[2][4][2];
        uint32_t aTb = aT[buf], bTb = bT[buf];

        #pragma unroll
        for (int mt = 0; mt < 2; mt++)
            ldsm_x4(aTb + swzA[mt], afr[0][mt]);
        #pragma unroll
        for (int nt2 = 0; nt2 < 2; nt2++) {
            uint32_t r[4];
            ldsm_x4_t(bTb + swzB[nt2], r);
            bfr[0][nt2 * 2][0] = r[0]; bfr[0][nt2 * 2][1] = r[1];
            bfr[0][nt2 * 2 + 1][0] = r[2]; bfr[0][nt2 * 2 + 1][1] = r[3];
        }

        #pragma unroll
        for (int ks = 0; ks < 4; ks++) {
            int cur = ks & 1, nxt = cur ^ 1;
            if (ks < 3) {
                int kk = (ks + 1) * 16;
                #pragma unroll
                for (int mt = 0; mt < 2; mt++)
                    ldsm_x4(aTb + (swzA[mt] ^ (uint32_t)(kk << 1)), afr[nxt][mt]);
                #pragma unroll
                for (int nt2 = 0; nt2 < 2; nt2++) {
                    uint32_t r[4];
                    ldsm_x4_t(bTb + swzB[nt2] + (uint32_t)(kk << 7), r);
                    bfr[nxt][nt2 * 2][0] = r[0]; bfr[nxt][nt2 * 2][1] = r[1];
                    bfr[nxt][nt2 * 2 + 1][0] = r[2]; bfr[nxt][nt2 * 2 + 1][1] = r[3];
                }
            }
            #pragma unroll
            for (int mt = 0; mt < 2; mt++)
                #pragma unroll
                for (int nt = 0; nt < 4; nt++)
                    mma_bf16(c[mt][nt], afr[cur][mt], bfr[cur][nt]);
        }
        __syncthreads();
    }

    #pragma unroll
    for (int mt = 0; mt < 2; mt++) {
        int row0 = m0 + wm + mt * 16 + (lane >> 2);
        #pragma unroll
        for (int nt = 0; nt < 4; nt++) {
            int col = n0 + wn + nt * 8 + (lane & 3) * 2;
            *(float2*)&Oo[(size_t)row0 * D + col] = make_float2(c[mt][nt][0], c[mt][nt][1]);
            *(float2*)&Oo[(size_t)(row0 + 8) * D + col] = make_float2(c[mt][nt][2], c[mt][nt][3]);
        }
    }
}

// ---------------- kernel 4: elu(0.5*(ΣO+h)), row-normalize, +bias ---------
__global__ void __launch_bounds__(256) k_final(const float* __restrict__ bias,
                                               float* __restrict__ out) {
    int i = blockIdx.x;
    int d = threadIdx.x;
    int lane = d & 31, warp = d >> 5;
    size_t idx = (size_t)i * D + d;
    float acc = g_h[idx];
    #pragma unroll
    for (int z = 0; z < KSPLIT; z++) acc += g_Op[(size_t)z * N * D + idx];
    float v = 0.5f * acc;
    float u = v > 0.f ? v : expm1f(v);

    float ss = u * u;
    #pragma unroll
    for (int s = 16; s > 0; s >>= 1) ss += __shfl_down_sync(0xFFFFFFFFu, ss, s);
    __shared__ float rw[8];
    if (lane == 0) rw[warp] = ss;
    __syncthreads();
    __shared__ float nrm;
    if (d == 0) {
        float t = 0.f;
        #pragma unroll
        for (int w = 0; w < 8; w++) t += rw[w];
        nrm = fmaxf(sqrtf(t), 1e-12f);
    }
    __syncthreads();
    out[idx] = u / nrm + bias[d];
}

// ---------------- launcher ----------------
extern "C" void kernel_launch(void* const* d_in, const int* in_sizes, int n_in,
                              void* d_out, int out_size) {
    const float* x   = (const float*)d_in[0];
    const int*   adj = (const int*)d_in[1];
    const float* cw  = (const float*)d_in[2];
    const float* cb  = (const float*)d_in[3];
    const float* a   = (const float*)d_in[4];
    const float* bias= (const float*)d_in[5];
    float* out = (float*)d_out;

    k_prep<<<N, D>>>(x, cw, cb, a);
    k_row<<<N, 256>>>(adj);

    int smem_gemm = 3 * (ABYTES + BBYTES);       // 73728
    cudaFuncSetAttribute(k_gemm_mma, cudaFuncAttributeMaxDynamicSharedMemorySize, smem_gemm);
    dim3 grid(D / BN, N / BM, KSPLIT);           // (4, 32, 4) = 512 CTAs
    k_gemm_mma<<<grid, 256, smem_gemm>>>();

    k_final<<<N, D>>>(bias, out);
}